// round 3
// baseline (speedup 1.0000x reference)
#include <cuda_runtime.h>

#define BN   8
#define CN   64
#define HN   256
#define WN   256
#define HP   257
#define WP   257
#define HWN  (HN * WN)          // 65536
#define NPIX (HP * WP)          // 66049
#define LN_EPS 1e-5f
#define NEG_SLOPE 0.01f

#define TLS   32                // output tile side
#define NT    9                 // tiles per dim (9*32=288 >= 257)
#define NTILE (NT * NT)         // 81 tiles per image
#define NBLK3 65                // ceil(66049/1024) for norm kernel

// Scratch (static device globals — allowed)
__device__ float g_cs[BN * HWN];          // channel sum        [8,256,256]
__device__ float g_y [BN * NPIX];         // pre-LN feature map [8,257,257]
__device__ float g_part[BN * NTILE * 2];  // per-tile (sum, sumsq)

// ---------------------------------------------------------------------------
// 1) Channel sum: cs[b,h,w] = sum_c x[b,c,h,w].  float4 vectorized.
// ---------------------------------------------------------------------------
__global__ void k_chansum(const float* __restrict__ x) {
    int t = blockIdx.x * blockDim.x + threadIdx.x;   // [0, BN*HWN/4)
    const int Q = HWN / 4;                            // 16384 float4 per plane
    int b  = t / Q;
    int p4 = t - b * Q;
    const float4* xp = reinterpret_cast<const float4*>(x) + (size_t)b * CN * Q + p4;
    float ax = 0.f, ay = 0.f, az = 0.f, aw = 0.f;
#pragma unroll 16
    for (int c = 0; c < CN; ++c) {
        float4 v = __ldg(xp + (size_t)c * Q);
        ax += v.x; ay += v.y; az += v.z; aw += v.w;
    }
    reinterpret_cast<float4*>(g_cs)[t] = make_float4(ax, ay, az, aw);
}

// ---------------------------------------------------------------------------
// 2) Fused: avg_pool(2,s1,p1) + 16-tap shift-pair stencil + bias + per-tile
//    partial sums for LayerNorm.  Grid (NT, NT, BN), block (32, 8).
//    Each block: 32x32 output tile, each thread 4 rows.
//    Zero-padded cs => pooled xs is exactly 0 outside [0,257)^2, so taps
//    need no bounds checks.
// ---------------------------------------------------------------------------
__global__ void k_feat(const float* __restrict__ cw, const float* __restrict__ cb) {
    __shared__ float s_cs[37][40];
    __shared__ float s_xs[36][40];
    __shared__ float s_w[8];
    __shared__ float red[256];

    const int tx = threadIdx.x, ty = threadIdx.y;
    const int tid = ty * 32 + tx;
    const int b  = blockIdx.z;
    const int i0 = blockIdx.y * TLS;
    const int j0 = blockIdx.x * TLS;

    if (tid < 8) s_w[tid] = cw[tid];
    const float bias = __ldg(cb);

    const float* __restrict__ cs = g_cs + (size_t)b * HWN;

    // Load cs halo tile: global rows [i0-3, i0+33], cols [j0-3, j0+33]
    for (int idx = tid; idx < 37 * 37; idx += 256) {
        int r = idx / 37, c = idx - r * 37;
        int gi = i0 - 3 + r, gj = j0 - 3 + c;
        float v = 0.f;
        if ((unsigned)gi < (unsigned)HN && (unsigned)gj < (unsigned)WN)
            v = cs[gi * WN + gj];
        s_cs[r][c] = v;
    }
    __syncthreads();

    // Pooled xs tile: s_xs[r][c] == xs(i0-2+r, j0-2+c), zero outside valid range
    for (int idx = tid; idx < 36 * 36; idx += 256) {
        int r = idx / 36, c = idx - r * 36;
        s_xs[r][c] = 0.25f * (s_cs[r][c] + s_cs[r][c + 1] +
                              s_cs[r + 1][c] + s_cs[r + 1][c + 1]);
    }
    __syncthreads();

    float* __restrict__ y = g_y + (size_t)b * NPIX;
    float lsum = 0.f, lsq = 0.f;

#pragma unroll
    for (int k = 0; k < 4; ++k) {
        int row = ty + 8 * k;            // local row in [0,32)
        int gi = i0 + row, gj = j0 + tx;
        if (gi < HP && gj < WP) {
            // tap(dr,dc) = s_xs[row+2+dr][tx+2+dc]
            const int R = row + 2, Cc = tx + 2;
            float v = bias;
            v += s_w[0] * (s_xs[R + 2][Cc + 2] - s_xs[R - 2][Cc - 2]);
            v += s_w[1] * (s_xs[R + 2][Cc + 1] - s_xs[R - 2][Cc - 1]);
            v += s_w[2] * (s_xs[R + 2][Cc    ] - s_xs[R - 2][Cc    ]);
            v += s_w[3] * (s_xs[R + 2][Cc - 1] - s_xs[R - 2][Cc + 1]);
            v += s_w[4] * (s_xs[R + 2][Cc - 2] - s_xs[R - 2][Cc + 2]);
            v += s_w[5] * (s_xs[R + 1][Cc - 2] - s_xs[R - 1][Cc + 2]);
            v += s_w[6] * (s_xs[R    ][Cc - 2] - s_xs[R    ][Cc + 2]);
            v += s_w[7] * (s_xs[R - 1][Cc - 2] - s_xs[R + 1][Cc + 2]);
            y[gi * WP + gj] = v;
            lsum += v;
            lsq  += v * v;
        }
    }

    // Deterministic block tree reductions
    red[tid] = lsum; __syncthreads();
#pragma unroll
    for (int s = 128; s > 0; s >>= 1) {
        if (tid < s) red[tid] += red[tid + s];
        __syncthreads();
    }
    int tileIdx = blockIdx.y * NT + blockIdx.x;
    if (tid == 0) g_part[(b * NTILE + tileIdx) * 2 + 0] = red[0];
    __syncthreads();

    red[tid] = lsq; __syncthreads();
#pragma unroll
    for (int s = 128; s > 0; s >>= 1) {
        if (tid < s) red[tid] += red[tid + s];
        __syncthreads();
    }
    if (tid == 0) g_part[(b * NTILE + tileIdx) * 2 + 1] = red[0];
}

// ---------------------------------------------------------------------------
// 3) Fused stats + normalize + LeakyReLU.  Grid (NBLK3, BN), 256 thr x 4 px.
//    Every block redundantly reduces the 81 per-tile partials for its image
//    (fixed serial order -> deterministic), then normalizes its chunk.
// ---------------------------------------------------------------------------
__global__ void k_norm(float* __restrict__ out) {
    const int b = blockIdx.y;
    const float* __restrict__ part = g_part + b * NTILE * 2;
    float a = 0.f, q = 0.f;
#pragma unroll 9
    for (int i = 0; i < NTILE; ++i) {
        a += part[i * 2 + 0];
        q += part[i * 2 + 1];
    }
    const float inv_n = 1.0f / (float)NPIX;
    const float mean = a * inv_n;
    const float istd = rsqrtf(q * inv_n - mean * mean + LN_EPS);

    const float* __restrict__ y = g_y + (size_t)b * NPIX;
    float* __restrict__ o = out + (size_t)b * NPIX;
#pragma unroll
    for (int k = 0; k < 4; ++k) {
        int p = blockIdx.x * 1024 + k * 256 + threadIdx.x;
        if (p < NPIX) {
            float v = (y[p] - mean) * istd;
            o[p] = v >= 0.f ? v : NEG_SLOPE * v;
        }
    }
}

// ---------------------------------------------------------------------------

extern "C" void kernel_launch(void* const* d_in, const int* in_sizes, int n_in,
                              void* d_out, int out_size) {
    const float* x  = (const float*)d_in[0];   // [8,64,256,256]
    const float* cw = (const float*)d_in[1];   // [1,8]
    const float* cb = (const float*)d_in[2];   // [1]
    float* out = (float*)d_out;                // [8,1,257,257]
    (void)in_sizes; (void)n_in; (void)out_size;

    k_chansum<<<(BN * HWN / 4) / 256, 256>>>(x);

    dim3 gfeat(NT, NT, BN), bfeat(32, 8);
    k_feat<<<gfeat, bfeat>>>(cw, cb);

    dim3 gnorm(NBLK3, BN);
    k_norm<<<gnorm, 256>>>(out);
}

// round 4
// speedup vs baseline: 1.2206x; 1.2206x over previous
#include <cuda_runtime.h>

#define BN   8
#define CN   64
#define HN   256
#define WN   256
#define HP   257
#define WP   257
#define HWN  (HN * WN)          // 65536
#define NPIX (HP * WP)          // 66049
#define LN_EPS 1e-5f
#define NEG_SLOPE 0.01f

// Padded xs buffer: logical xs(i,j), i,j in [0,257), stored at [(i+2), (j+2)]
// inside a 261-row x 264-stride plane whose border is zero. Taps at +/-2 then
// need no bounds checks.
#define HPP  261
#define WPP  261
#define WST  264                // row stride (alignment)
#define NPAD (HPP * WST)

#define NBLK 65                 // ceil(66049/1024) blocks per image (feat/norm)

// Scratch (static device globals — allowed)
__device__ float g_cs [BN * HWN];         // channel sum          [8,256,256]
__device__ float g_xsp[BN * NPAD];        // padded pooled sum
__device__ float g_y  [BN * NPIX];        // pre-LN feature map   [8,257,257]
__device__ float g_part[BN * NBLK * 2];   // per-block (sum, sumsq)

// ---------------------------------------------------------------------------
// 1) Channel sum, float4 vectorized. 2048 blocks x 64 threads for wave balance
//    (13-14 blocks/SM instead of 3-4 -> <=7% tail imbalance).
// ---------------------------------------------------------------------------
__global__ void k_chansum(const float* __restrict__ x) {
    int t = blockIdx.x * 64 + threadIdx.x;           // [0, BN*HWN/4)
    const int Q = HWN / 4;                            // 16384 float4 per plane
    int b  = t / Q;
    int p4 = t - b * Q;
    const float4* xp = reinterpret_cast<const float4*>(x) + (size_t)b * CN * Q + p4;
    float ax = 0.f, ay = 0.f, az = 0.f, aw = 0.f;
#pragma unroll 16
    for (int c = 0; c < CN; ++c) {
        float4 v = __ldg(xp + (size_t)c * Q);
        ax += v.x; ay += v.y; az += v.z; aw += v.w;
    }
    reinterpret_cast<float4*>(g_cs)[t] = make_float4(ax, ay, az, aw);
}

// ---------------------------------------------------------------------------
// 2) avg_pool2d(k=2,s=1,p=1,count_include_pad) -> padded xs buffer.
//    Covers the whole padded plane; outside the valid xs range writes 0.
// ---------------------------------------------------------------------------
__global__ void k_pool() {
    int t = blockIdx.x * blockDim.x + threadIdx.x;
    const int NP = HPP * WPP;                         // 261*261 logical pixels
    if (t >= BN * NP) return;
    int b = t / NP;
    int p = t - b * NP;
    int pi = p / WPP;                                 // padded row [0,261)
    int pj = p - pi * WPP;                            // padded col [0,261)
    int i = pi - 2, j = pj - 2;                       // xs coords

    float v = 0.f;
    if ((unsigned)i < (unsigned)HP && (unsigned)j < (unsigned)WP) {
        const float* cs = g_cs + (size_t)b * HWN;
        float s = 0.f;
        int r0 = i - 1, c0 = j - 1;
        bool vr0 = (unsigned)r0 < (unsigned)HN, vr1 = (unsigned)i < (unsigned)HN;
        bool vc0 = (unsigned)c0 < (unsigned)WN, vc1 = (unsigned)j < (unsigned)WN;
        if (vr0) {
            const float* row = cs + r0 * WN;
            if (vc0) s += row[c0];
            if (vc1) s += row[j];
        }
        if (vr1) {
            const float* row = cs + i * WN;
            if (vc0) s += row[c0];
            if (vc1) s += row[j];
        }
        v = s * 0.25f;
    }
    g_xsp[(size_t)b * NPAD + pi * WST + pj] = v;
}

// ---------------------------------------------------------------------------
// 3) 16-tap stencil + bias + per-block LN partials (warp-shuffle reduction).
//    Grid (NBLK, BN), 256 threads x 4 pixels. Taps are unconditional reads
//    from the zero-padded xs plane (L2-resident).
// ---------------------------------------------------------------------------
__global__ void k_feat(const float* __restrict__ cw, const float* __restrict__ cb) {
    __shared__ float s_w[8];
    __shared__ float s_red[8][2];
    const int tid = threadIdx.x;
    const int b   = blockIdx.y;
    if (tid < 8) s_w[tid] = cw[tid];
    __syncthreads();
    const float bias = __ldg(cb);

    const float* __restrict__ xs = g_xsp + (size_t)b * NPAD;
    float*       __restrict__ y  = g_y   + (size_t)b * NPIX;

    float lsum = 0.f, lsq = 0.f;
#pragma unroll
    for (int k = 0; k < 4; ++k) {
        int p = blockIdx.x * 1024 + k * 256 + tid;
        if (p < NPIX) {
            int h  = p / WP;
            int wi = p - h * WP;
            const float* c = xs + (h + 2) * WST + (wi + 2);   // padded center
            float v = bias;
            v += s_w[0] * (__ldg(c + 2 * WST + 2) - __ldg(c - 2 * WST - 2));
            v += s_w[1] * (__ldg(c + 2 * WST + 1) - __ldg(c - 2 * WST - 1));
            v += s_w[2] * (__ldg(c + 2 * WST    ) - __ldg(c - 2 * WST    ));
            v += s_w[3] * (__ldg(c + 2 * WST - 1) - __ldg(c - 2 * WST + 1));
            v += s_w[4] * (__ldg(c + 2 * WST - 2) - __ldg(c - 2 * WST + 2));
            v += s_w[5] * (__ldg(c + 1 * WST - 2) - __ldg(c - 1 * WST + 2));
            v += s_w[6] * (__ldg(c           - 2) - __ldg(c           + 2));
            v += s_w[7] * (__ldg(c - 1 * WST - 2) - __ldg(c + 1 * WST + 2));
            y[p] = v;
            lsum += v;
            lsq  += v * v;
        }
    }

    // Deterministic reduction: warp shuffle tree, then warp 0 combines.
#pragma unroll
    for (int o = 16; o > 0; o >>= 1) {
        lsum += __shfl_down_sync(0xffffffffu, lsum, o);
        lsq  += __shfl_down_sync(0xffffffffu, lsq,  o);
    }
    int wid = tid >> 5, lane = tid & 31;
    if (lane == 0) { s_red[wid][0] = lsum; s_red[wid][1] = lsq; }
    __syncthreads();
    if (tid == 0) {
        float a = 0.f, q = 0.f;
#pragma unroll
        for (int w = 0; w < 8; ++w) { a += s_red[w][0]; q += s_red[w][1]; }
        g_part[(b * NBLK + blockIdx.x) * 2 + 0] = a;
        g_part[(b * NBLK + blockIdx.x) * 2 + 1] = q;
    }
}

// ---------------------------------------------------------------------------
// 4) Fused stats + normalize + LeakyReLU.  Grid (NBLK, BN), 256 thr x 4 px.
//    Every block redundantly reduces its image's 65 partial pairs (fixed
//    serial order -> deterministic; L2-resident), then normalizes its chunk.
// ---------------------------------------------------------------------------
__global__ void k_norm(float* __restrict__ out) {
    const int b = blockIdx.y;
    const float* __restrict__ part = g_part + b * NBLK * 2;
    float a = 0.f, q = 0.f;
#pragma unroll 13
    for (int i = 0; i < NBLK; ++i) {
        a += part[i * 2 + 0];
        q += part[i * 2 + 1];
    }
    const float inv_n = 1.0f / (float)NPIX;
    const float mean = a * inv_n;
    const float istd = rsqrtf(q * inv_n - mean * mean + LN_EPS);

    const float* __restrict__ y = g_y + (size_t)b * NPIX;
    float* __restrict__ o = out + (size_t)b * NPIX;
#pragma unroll
    for (int k = 0; k < 4; ++k) {
        int p = blockIdx.x * 1024 + k * 256 + threadIdx.x;
        if (p < NPIX) {
            float v = (y[p] - mean) * istd;
            o[p] = v >= 0.f ? v : NEG_SLOPE * v;
        }
    }
}

// ---------------------------------------------------------------------------

extern "C" void kernel_launch(void* const* d_in, const int* in_sizes, int n_in,
                              void* d_out, int out_size) {
    const float* x  = (const float*)d_in[0];   // [8,64,256,256]
    const float* cw = (const float*)d_in[1];   // [1,8]
    const float* cb = (const float*)d_in[2];   // [1]
    float* out = (float*)d_out;                // [8,1,257,257]
    (void)in_sizes; (void)n_in; (void)out_size;

    // 1) channel sum: 131072 threads in 2048 small blocks (wave balance)
    k_chansum<<<2048, 64>>>(x);

    // 2) pool into padded xs plane
    int n_pad = BN * HPP * WPP;
    k_pool<<<(n_pad + 255) / 256, 256>>>();

    // 3) stencil + LN partials
    dim3 gfeat(NBLK, BN);
    k_feat<<<gfeat, 256>>>(cw, cb);

    // 4) stats + normalize + leaky relu
    k_norm<<<gfeat, 256>>>(out);
}